// round 7
// baseline (speedup 1.0000x reference)
#include <cuda_runtime.h>
#include <cuda_fp16.h>

#define FRAME_NUMBER 16
#define FRAME_SIZE   128
#define SAMPLE_NUM   16
#define NUM_EVENTS   1048576
#define EV_PER_FRAME (NUM_EVENTS / FRAME_NUMBER)      /* 65536 */
#define BINS         (FRAME_SIZE * FRAME_SIZE)        /* 16384 bins */

// Scratch: packed bin id (y*128 + x) per event, u16 (bin < 16384). 2 MB.
__device__ unsigned short g_bins[NUM_EVENTS];

// ---------------------------------------------------------------------------
// Prepass: pack (x, y) -> u16 bin, handling int64 OR int32 index dtype.
// Detection: view buffer as int32. If dtype is int64, words [N-1],[N-3],... are
// HIGH words of mid-range sorted t values -> all zero. If int32, those words
// are the tail of the sorted t row (~65535) -> nonzero.
// ---------------------------------------------------------------------------
__global__ __launch_bounds__(256)
void bins_kernel(const int* __restrict__ idx32) {
    const int e = (blockIdx.x * blockDim.x + threadIdx.x) * 4;  // first event
    const bool is64 = (idx32[NUM_EVENTS - 1] == 0) &&
                      (idx32[NUM_EVENTS - 3] == 0) &&
                      (idx32[NUM_EVENTS - 5] == 0) &&
                      (idx32[NUM_EVENTS - 7] == 0);
    int x0, x1, x2, x3, y0, y1, y2, y3;
    if (is64) {
        const longlong2* __restrict__ px =
            reinterpret_cast<const longlong2*>(idx32) + (NUM_EVENTS + e) / 2;
        const longlong2* __restrict__ py =
            reinterpret_cast<const longlong2*>(idx32) + (2 * NUM_EVENTS + e) / 2;
        longlong2 xa = px[0], xb = px[1];
        longlong2 ya = py[0], yb = py[1];
        x0 = (int)xa.x; x1 = (int)xa.y; x2 = (int)xb.x; x3 = (int)xb.y;
        y0 = (int)ya.x; y1 = (int)ya.y; y2 = (int)yb.x; y3 = (int)yb.y;
    } else {
        const int4 x4 = *reinterpret_cast<const int4*>(idx32 + NUM_EVENTS + e);
        const int4 y4 = *reinterpret_cast<const int4*>(idx32 + 2 * NUM_EVENTS + e);
        x0 = x4.x; x1 = x4.y; x2 = x4.z; x3 = x4.w;
        y0 = y4.x; y1 = y4.y; y2 = y4.z; y3 = y4.w;
    }
    ushort4 o;
    o.x = (unsigned short)(y0 * FRAME_SIZE + x0);
    o.y = (unsigned short)(y1 * FRAME_SIZE + x1);
    o.z = (unsigned short)(y2 * FRAME_SIZE + x2);
    o.w = (unsigned short)(y3 * FRAME_SIZE + x3);
    *reinterpret_cast<ushort4*>(g_bins + e) = o;
}

// ---------------------------------------------------------------------------
// Main: one CTA per (frame, sample). Histogram packs BOTH channels as one
// __half2 per bin (.x = neg ch, .y = pos ch) -> 64 KB smem -> 2 CTAs/SM,
// 64 warps feeding the ATOMS pipe with the SAME one-atomic-per-event loop
// as the f32 champion (ATOMS.ADD.F16x2: no dead lanes, no extra ALU).
// Writeback converts to two coalesced f32 channel planes.
// out[f, s, c, y, x] : flat = (f*S + s)*32768 + c*16384 + y*128 + x
// ---------------------------------------------------------------------------
#define TPB      1024
#define EV_PER_T 4                          /* events per thread per chunk */
#define CHUNK    (TPB * EV_PER_T)           /* 4096 */
#define NITER    (EV_PER_FRAME / CHUNK)     /* 16 */

__device__ __forceinline__ void scat_h2(__half2* hist, float v, unsigned bin) {
    const __half2 h = __floats2half2_rn(fmaxf(-v, 0.0f), fmaxf(v, 0.0f));
    atomicAdd(&hist[bin], h);
}

__global__ __launch_bounds__(TPB, 2)
void accum_kernel(const float* __restrict__ vals, float* __restrict__ out) {
    extern __shared__ __half2 hist[];       // BINS half2 = 64 KB
    const int f = blockIdx.x;
    const int s = blockIdx.y;

    // zero histogram (uint4 stores: 16384 half2 = 4096 uint4)
    {
        uint4 z = make_uint4(0u, 0u, 0u, 0u);
        uint4* h4 = reinterpret_cast<uint4*>(hist);
        #pragma unroll
        for (int i = threadIdx.x; i < BINS / 4; i += TPB) h4[i] = z;
    }
    __syncthreads();

    const float* __restrict__ v =
        vals + (size_t)s * NUM_EVENTS + (size_t)f * EV_PER_FRAME;
    const unsigned short* __restrict__ b = g_bins + f * EV_PER_FRAME;
    const int t4 = threadIdx.x * EV_PER_T;

    // lean double buffer (fits 32 regs at occupancy 2)
    float4 cv = *reinterpret_cast<const float4*>(v + t4);
    uint2  cb = *reinterpret_cast<const uint2*>(b + t4);

    #pragma unroll
    for (int it = 0; it < NITER; ++it) {
        float4 nv; uint2 nb;
        if (it + 1 < NITER) {
            const int idx = (it + 1) * CHUNK + t4;
            nv = *reinterpret_cast<const float4*>(v + idx);
            nb = *reinterpret_cast<const uint2*>(b + idx);
        }
        scat_h2(hist, cv.x, cb.x & 0xFFFFu);
        scat_h2(hist, cv.y, cb.x >> 16);
        scat_h2(hist, cv.z, cb.y & 0xFFFFu);
        scat_h2(hist, cv.w, cb.y >> 16);
        if (it + 1 < NITER) { cv = nv; cb = nb; }
    }
    __syncthreads();

    // writeback: half2 -> two f32 channel planes, float4-coalesced.
    float* __restrict__ o0 = out + (size_t)(f * SAMPLE_NUM + s) * (2 * BINS);
    float* __restrict__ o1 = o0 + BINS;
    #pragma unroll
    for (int i = threadIdx.x * 4; i < BINS; i += TPB * 4) {
        // 4 bins: 4 half2 = one uint4 from smem
        const uint4 raw = *reinterpret_cast<const uint4*>(hist + i);
        const __half2 h0 = *reinterpret_cast<const __half2*>(&raw.x);
        const __half2 h1 = *reinterpret_cast<const __half2*>(&raw.y);
        const __half2 h2 = *reinterpret_cast<const __half2*>(&raw.z);
        const __half2 h3 = *reinterpret_cast<const __half2*>(&raw.w);
        float4 c0, c1;
        c0.x = __low2float(h0);  c1.x = __high2float(h0);
        c0.y = __low2float(h1);  c1.y = __high2float(h1);
        c0.z = __low2float(h2);  c1.z = __high2float(h2);
        c0.w = __low2float(h3);  c1.w = __high2float(h3);
        *reinterpret_cast<float4*>(o0 + i) = c0;
        *reinterpret_cast<float4*>(o1 + i) = c1;
    }
}

extern "C" void kernel_launch(void* const* d_in, const int* in_sizes, int n_in,
                              void* d_out, int out_size) {
    (void)in_sizes; (void)n_in; (void)out_size;
    const float* vals  = (const float*)d_in[0];
    const int*   idx32 = (const int*)d_in[1];   // raw view; dtype detected on device
    float*       out   = (float*)d_out;

    cudaFuncSetAttribute(accum_kernel,
                         cudaFuncAttributeMaxDynamicSharedMemorySize,
                         BINS * (int)sizeof(__half2));

    bins_kernel<<<NUM_EVENTS / (256 * 4), 256>>>(idx32);
    accum_kernel<<<dim3(FRAME_NUMBER, SAMPLE_NUM), TPB,
                   BINS * sizeof(__half2)>>>(vals, out);
}

// round 8
// speedup vs baseline: 1.5846x; 1.5846x over previous
#include <cuda_runtime.h>

#define FRAME_NUMBER 16
#define FRAME_SIZE   128
#define SAMPLE_NUM   16
#define NUM_EVENTS   1048576
#define EV_PER_FRAME (NUM_EVENTS / FRAME_NUMBER)      /* 65536 */
#define BINS         (FRAME_SIZE * FRAME_SIZE)        /* 16384 */
#define HIST         (2 * BINS)                       /* 32768 floats = 128 KB */

// Scratch: packed bin id (y*128 + x) per event, u16 (bin < 16384). 2 MB.
__device__ unsigned short g_bins[NUM_EVENTS];

// ---------------------------------------------------------------------------
// Prepass: pack (x, y) -> u16 bin, handling int64 OR int32 index dtype.
// Detection: view buffer as int32. If dtype is int64, words [N-1],[N-3],... are
// HIGH words of mid-range sorted t values -> all zero. If int32, those words
// are the tail of the sorted t row (~65535) -> nonzero.
// ---------------------------------------------------------------------------
__global__ __launch_bounds__(256)
void bins_kernel(const int* __restrict__ idx32) {
    const int e = (blockIdx.x * blockDim.x + threadIdx.x) * 4;  // first event
    const bool is64 = (idx32[NUM_EVENTS - 1] == 0) &&
                      (idx32[NUM_EVENTS - 3] == 0) &&
                      (idx32[NUM_EVENTS - 5] == 0) &&
                      (idx32[NUM_EVENTS - 7] == 0);
    int x0, x1, x2, x3, y0, y1, y2, y3;
    if (is64) {
        const longlong2* __restrict__ px =
            reinterpret_cast<const longlong2*>(idx32) + (NUM_EVENTS + e) / 2;
        const longlong2* __restrict__ py =
            reinterpret_cast<const longlong2*>(idx32) + (2 * NUM_EVENTS + e) / 2;
        longlong2 xa = px[0], xb = px[1];
        longlong2 ya = py[0], yb = py[1];
        x0 = (int)xa.x; x1 = (int)xa.y; x2 = (int)xb.x; x3 = (int)xb.y;
        y0 = (int)ya.x; y1 = (int)ya.y; y2 = (int)yb.x; y3 = (int)yb.y;
    } else {
        const int4 x4 = *reinterpret_cast<const int4*>(idx32 + NUM_EVENTS + e);
        const int4 y4 = *reinterpret_cast<const int4*>(idx32 + 2 * NUM_EVENTS + e);
        x0 = x4.x; x1 = x4.y; x2 = x4.z; x3 = x4.w;
        y0 = y4.x; y1 = y4.y; y2 = y4.z; y3 = y4.w;
    }
    ushort4 o;
    o.x = (unsigned short)(y0 * FRAME_SIZE + x0);
    o.y = (unsigned short)(y1 * FRAME_SIZE + x1);
    o.z = (unsigned short)(y2 * FRAME_SIZE + x2);
    o.w = (unsigned short)(y3 * FRAME_SIZE + x3);
    *reinterpret_cast<ushort4*>(g_bins + e) = o;
}

// ---------------------------------------------------------------------------
// Main: one CTA per (frame, sample). Full 2x128x128 f32 histogram in dynamic
// smem (128 KB), one |v| atomic per event to the sign-selected channel.
// EV_PER_T=8: all 8 (address, weight) pairs computed up front, then 8
// back-to-back ATOMS (deepens the L1 atomic unit's in-flight pipeline).
// DEPTH=3 rotating prefetch keeps loads ~1.5x DRAM latency ahead.
// out[f, s, c, y, x] : flat = (f*S + s)*32768 + c*16384 + y*128 + x
// ---------------------------------------------------------------------------
#define TPB      1024
#define EV_PER_T 8                          /* events per thread per chunk */
#define CHUNK    (TPB * EV_PER_T)           /* 8192 */
#define NITER    (EV_PER_FRAME / CHUNK)     /* 8 */
#define DEPTH    3                          /* prefetch distance */

__global__ __launch_bounds__(TPB, 1)
void accum_kernel(const float* __restrict__ vals, float* __restrict__ out) {
    extern __shared__ float hist[];   // HIST floats = 128 KB
    const int f = blockIdx.x;
    const int s = blockIdx.y;

    // zero histogram
    {
        float4 z = make_float4(0.f, 0.f, 0.f, 0.f);
        float4* h4 = reinterpret_cast<float4*>(hist);
        #pragma unroll
        for (int i = threadIdx.x; i < HIST / 4; i += TPB) h4[i] = z;
    }
    __syncthreads();

    const float* __restrict__ v =
        vals + (size_t)s * NUM_EVENTS + (size_t)f * EV_PER_FRAME;
    const unsigned short* __restrict__ b = g_bins + f * EV_PER_FRAME;
    const int t8 = threadIdx.x * EV_PER_T;

    float4 vb0[DEPTH], vb1[DEPTH];
    uint4  bb[DEPTH];

    // prologue: fill pipeline DEPTH chunks deep
    #pragma unroll
    for (int d = 0; d < DEPTH; ++d) {
        const int idx = d * CHUNK + t8;
        vb0[d] = __ldcs(reinterpret_cast<const float4*>(v + idx));
        vb1[d] = __ldcs(reinterpret_cast<const float4*>(v + idx + 4));
        bb[d]  = *reinterpret_cast<const uint4*>(b + idx);
    }

    #pragma unroll
    for (int it = 0; it < NITER; ++it) {
        const int slot = it % DEPTH;
        const float4 cv0 = vb0[slot];
        const float4 cv1 = vb1[slot];
        const uint4  cb  = bb[slot];
        if (it + DEPTH < NITER) {
            const int idx = (it + DEPTH) * CHUNK + t8;
            vb0[slot] = __ldcs(reinterpret_cast<const float4*>(v + idx));
            vb1[slot] = __ldcs(reinterpret_cast<const float4*>(v + idx + 4));
            bb[slot]  = *reinterpret_cast<const uint4*>(b + idx);
        }

        // compute all 8 target addresses + weights, then burst 8 ATOMS
        float w[8]; int a[8];
        w[0] = fabsf(cv0.x); a[0] = (cv0.x > 0.f ? BINS : 0) + (int)(cb.x & 0xFFFFu);
        w[1] = fabsf(cv0.y); a[1] = (cv0.y > 0.f ? BINS : 0) + (int)(cb.x >> 16);
        w[2] = fabsf(cv0.z); a[2] = (cv0.z > 0.f ? BINS : 0) + (int)(cb.y & 0xFFFFu);
        w[3] = fabsf(cv0.w); a[3] = (cv0.w > 0.f ? BINS : 0) + (int)(cb.y >> 16);
        w[4] = fabsf(cv1.x); a[4] = (cv1.x > 0.f ? BINS : 0) + (int)(cb.z & 0xFFFFu);
        w[5] = fabsf(cv1.y); a[5] = (cv1.y > 0.f ? BINS : 0) + (int)(cb.z >> 16);
        w[6] = fabsf(cv1.z); a[6] = (cv1.z > 0.f ? BINS : 0) + (int)(cb.w & 0xFFFFu);
        w[7] = fabsf(cv1.w); a[7] = (cv1.w > 0.f ? BINS : 0) + (int)(cb.w >> 16);
        #pragma unroll
        for (int j = 0; j < 8; ++j) atomicAdd(&hist[a[j]], w[j]);
    }
    __syncthreads();

    // coalesced writeback
    float4* __restrict__ o =
        reinterpret_cast<float4*>(out + (size_t)(f * SAMPLE_NUM + s) * HIST);
    const float4* h4 = reinterpret_cast<const float4*>(hist);
    #pragma unroll
    for (int i = threadIdx.x; i < HIST / 4; i += TPB) o[i] = h4[i];
}

extern "C" void kernel_launch(void* const* d_in, const int* in_sizes, int n_in,
                              void* d_out, int out_size) {
    (void)in_sizes; (void)n_in; (void)out_size;
    const float* vals  = (const float*)d_in[0];
    const int*   idx32 = (const int*)d_in[1];   // raw view; dtype detected on device
    float*       out   = (float*)d_out;

    cudaFuncSetAttribute(accum_kernel,
                         cudaFuncAttributeMaxDynamicSharedMemorySize,
                         HIST * (int)sizeof(float));

    bins_kernel<<<NUM_EVENTS / (256 * 4), 256>>>(idx32);
    accum_kernel<<<dim3(FRAME_NUMBER, SAMPLE_NUM), TPB, HIST * sizeof(float)>>>(vals, out);
}